// round 1
// baseline (speedup 1.0000x reference)
#include <cuda_runtime.h>
#include <math.h>

// ---------------- problem constants (fixed-shape problem) ----------------
#define N_MICRO_MAX 500000
#define MICRO_DIM   512
#define N_NODES_C   20000
#define N_EDGES_C   40000
#define NSEG        60000          // N_NODES + N_EDGES (unified segment space)
#define NSEG_PAD    60032          // 469 * 128 (GEMM M tiles)
#define EPS_SM      1e-8f
#define EPS_LN      1e-5f

#define CHUNK       1024
#define NB_CHUNK    59             // ceil(NSEG / CHUNK)

#define CACHE_ROWS  20             // rows cached in SMEM per segment
#define MAX_SH      1024           // max logits held in SMEM (fallback beyond)

// ---------------- device scratch (no allocations allowed) ----------------
__device__ int   g_counts[NSEG];
__device__ int   g_offsets[NSEG];
__device__ int   g_cursor[NSEG];
__device__ int   g_bsum[NB_CHUNK];
__device__ int   g_rows[N_MICRO_MAX];
__device__ float g_agg[(size_t)NSEG_PAD * MICRO_DIM];   // ~123 MB, zero-init; pad rows never written

// ---------------- helpers ----------------
__device__ __forceinline__ int seg_of(int m) {
    if (m >= 0) return m;               // node id
    if (m == -100) return -1;           // masked (note: also drops edge id 99 — matches reference)
    return N_NODES_C + (-m - 1);        // edge id
}

// ---------------- 0) init scratch ----------------
__global__ void init_kernel() {
    int i = blockIdx.x * blockDim.x + threadIdx.x;
    if (i < NSEG) { g_counts[i] = 0; g_cursor[i] = 0; }
}

// ---------------- 1) count per segment ----------------
__global__ void count_kernel(const int* __restrict__ m2m, int n) {
    int i = blockIdx.x * blockDim.x + threadIdx.x;
    if (i < n) {
        int s = seg_of(m2m[i]);
        if (s >= 0) atomicAdd(&g_counts[s], 1);
    }
}

// ---------------- 2) scan: chunk sums -> scan sums -> chunk scan ----------------
__global__ void sum_chunks_kernel() {
    __shared__ int sh[256];
    int b = blockIdx.x, t = threadIdx.x;
    int base = b * CHUNK;
    int s = 0;
    for (int j = t; j < CHUNK; j += 256) {
        int i = base + j;
        if (i < NSEG) s += g_counts[i];
    }
    sh[t] = s; __syncthreads();
    for (int d = 128; d; d >>= 1) { if (t < d) sh[t] += sh[t + d]; __syncthreads(); }
    if (t == 0) g_bsum[b] = sh[0];
}

__global__ void scan_bsums_kernel() {
    if (threadIdx.x == 0 && blockIdx.x == 0) {
        int c = 0;
        for (int b = 0; b < NB_CHUNK; b++) { int v = g_bsum[b]; g_bsum[b] = c; c += v; }
    }
}

__global__ void scan_chunks_kernel() {
    int b = blockIdx.x, lane = threadIdx.x;  // 32 threads
    int base = b * CHUNK + lane * 32;
    int vals[32];
    int lsum = 0;
    #pragma unroll
    for (int j = 0; j < 32; j++) {
        int i = base + j;
        vals[j] = (i < NSEG) ? g_counts[i] : 0;
        lsum += vals[j];
    }
    int pre = lsum;
    #pragma unroll
    for (int d = 1; d < 32; d <<= 1) {
        int x = __shfl_up_sync(0xffffffffu, pre, d);
        if (lane >= d) pre += x;
    }
    pre -= lsum;  // exclusive
    int carry = g_bsum[b] + pre;
    #pragma unroll
    for (int j = 0; j < 32; j++) {
        int i = base + j;
        if (i < NSEG) g_offsets[i] = carry;
        carry += vals[j];
    }
}

// ---------------- 3) scatter row ids into CSR ----------------
__global__ void scatter_kernel(const int* __restrict__ m2m, int n) {
    int i = blockIdx.x * blockDim.x + threadIdx.x;
    if (i < n) {
        int s = seg_of(m2m[i]);
        if (s >= 0) {
            int pos = g_offsets[s] + atomicAdd(&g_cursor[s], 1);
            g_rows[pos] = i;
        }
    }
}

// ---------------- 4) per-segment fused logits + softmax + weighted sum ----------------
__global__ void __launch_bounds__(256)
agg_kernel(const float* __restrict__ feat,
           const float* __restrict__ attn_w,
           const float* __restrict__ attn_bp) {
    __shared__ float s_aw[MICRO_DIM];
    __shared__ float s_rows[CACHE_ROWS][MICRO_DIM];
    __shared__ float s_logit[MAX_SH];
    __shared__ float s_red[8];

    int seg  = blockIdx.x;
    int tid  = threadIdx.x;
    int lane = tid & 31, wid = tid >> 5;
    int cnt  = g_counts[seg];
    int off  = g_offsets[seg];
    int c0 = tid, c1 = tid + 256;
    size_t outbase = (size_t)seg * MICRO_DIM;

    if (cnt == 0) {                          // uniform across block
        g_agg[outbase + c0] = 0.f;
        g_agg[outbase + c1] = 0.f;
        return;
    }

    for (int j = tid; j < MICRO_DIM; j += 256) s_aw[j] = attn_w[j];
    __syncthreads();
    float ab = attn_bp[0];
    float acc0 = 0.f, acc1 = 0.f;

    if (cnt <= MAX_SH) {
        // phase 1: one warp per row — load row, dot with attn_w, cache row
        for (int r = wid; r < cnt; r += 8) {
            int row = g_rows[off + r];
            const float4* fp = (const float4*)(feat + (size_t)row * MICRO_DIM);
            float dot = 0.f;
            bool cache = (r < CACHE_ROWS);
            #pragma unroll
            for (int k = 0; k < 4; k++) {
                float4 v = fp[lane + 32 * k];
                int j = (lane + 32 * k) * 4;
                dot += v.x * s_aw[j] + v.y * s_aw[j + 1] + v.z * s_aw[j + 2] + v.w * s_aw[j + 3];
                if (cache) ((float4*)s_rows[r])[lane + 32 * k] = v;
            }
            #pragma unroll
            for (int d = 16; d; d >>= 1) dot += __shfl_xor_sync(0xffffffffu, dot, d);
            if (lane == 0) s_logit[r] = dot + ab;
        }
        __syncthreads();

        // phase 2a: block max
        float m = -INFINITY;
        for (int r = tid; r < cnt; r += 256) m = fmaxf(m, s_logit[r]);
        #pragma unroll
        for (int d = 16; d; d >>= 1) m = fmaxf(m, __shfl_xor_sync(0xffffffffu, m, d));
        if (lane == 0) s_red[wid] = m;
        __syncthreads();
        m = s_red[0];
        #pragma unroll
        for (int w = 1; w < 8; w++) m = fmaxf(m, s_red[w]);
        __syncthreads();   // protect s_red reuse

        // phase 2b: exp + block sum
        float ssum = 0.f;
        for (int r = tid; r < cnt; r += 256) {
            float e = expf(s_logit[r] - m);
            s_logit[r] = e;
            ssum += e;
        }
        #pragma unroll
        for (int d = 16; d; d >>= 1) ssum += __shfl_xor_sync(0xffffffffu, ssum, d);
        if (lane == 0) s_red[wid] = ssum;
        __syncthreads();   // also makes all s_logit e-values visible
        float tot = 0.f;
        #pragma unroll
        for (int w = 0; w < 8; w++) tot += s_red[w];
        float inv = 1.f / (tot + EPS_SM);

        // phase 3: weighted accumulate (each thread owns 2 columns)
        for (int r = 0; r < cnt; r++) {
            float wgt = s_logit[r] * inv;
            if (r < CACHE_ROWS) {
                acc0 += wgt * s_rows[r][c0];
                acc1 += wgt * s_rows[r][c1];
            } else {
                int row = g_rows[off + r];
                acc0 += wgt * __ldg(feat + (size_t)row * MICRO_DIM + c0);
                acc1 += wgt * __ldg(feat + (size_t)row * MICRO_DIM + c1);
            }
        }
    } else {
        // general fallback: online softmax, whole block per row (statistically never taken)
        float m = -INFINITY, s = 0.f;
        for (int r = 0; r < cnt; r++) {
            int row = g_rows[off + r];
            const float* f = feat + (size_t)row * MICRO_DIM;
            float f0 = f[c0], f1 = f[c1];
            float p = f0 * s_aw[c0] + f1 * s_aw[c1];
            #pragma unroll
            for (int d = 16; d; d >>= 1) p += __shfl_xor_sync(0xffffffffu, p, d);
            if (lane == 0) s_red[wid] = p;
            __syncthreads();
            float l = ab;
            #pragma unroll
            for (int w = 0; w < 8; w++) l += s_red[w];
            __syncthreads();
            float mn = fmaxf(m, l);
            float sc = expf(m - mn);
            float e  = expf(l - mn);
            s    = s * sc + e;
            acc0 = acc0 * sc + e * f0;
            acc1 = acc1 * sc + e * f1;
            m = mn;
        }
        float inv = 1.f / (s + EPS_SM);
        acc0 *= inv; acc1 *= inv;
    }

    g_agg[outbase + c0] = acc0;
    g_agg[outbase + c1] = acc1;
}

// ---------------- 5) projection GEMM: h = agg @ W  (bias added in LN kernel) ----------------
#define BM 128
#define BN 128
#define BK 16
__global__ void __launch_bounds__(256)
gemm_kernel(const float* __restrict__ W, float* __restrict__ out, int M) {
    __shared__ float As[BK][BM];
    __shared__ float Bs[BK][BN];
    int tid = threadIdx.x;
    int tx = tid & 15, ty = tid >> 4;
    int rowBase = blockIdx.y * BM;
    int colBase = blockIdx.x * BN;
    float acc[8][8];
    #pragma unroll
    for (int i = 0; i < 8; i++)
        #pragma unroll
        for (int j = 0; j < 8; j++) acc[i][j] = 0.f;

    for (int k0 = 0; k0 < MICRO_DIM; k0 += BK) {
        #pragma unroll
        for (int l = 0; l < 2; l++) {                 // A tile: 512 float4, transposed into As[k][m]
            int f = tid + l * 256;
            int r = f >> 2;
            int c4 = f & 3;
            float4 v = *(const float4*)(g_agg + (size_t)(rowBase + r) * MICRO_DIM + k0 + c4 * 4);
            As[c4 * 4 + 0][r] = v.x;
            As[c4 * 4 + 1][r] = v.y;
            As[c4 * 4 + 2][r] = v.z;
            As[c4 * 4 + 3][r] = v.w;
        }
        #pragma unroll
        for (int l = 0; l < 2; l++) {                 // B tile: row-major direct
            int f = tid + l * 256;
            int r = f >> 5;
            int c = (f & 31) * 4;
            float4 v = *(const float4*)(W + (size_t)(k0 + r) * MICRO_DIM + colBase + c);
            *(float4*)&Bs[r][c] = v;
        }
        __syncthreads();
        #pragma unroll
        for (int k = 0; k < BK; k++) {
            float a[8], b[8];
            #pragma unroll
            for (int i = 0; i < 8; i++) a[i] = As[k][ty * 8 + i];
            #pragma unroll
            for (int j = 0; j < 8; j++) b[j] = Bs[k][tx * 8 + j];
            #pragma unroll
            for (int i = 0; i < 8; i++)
                #pragma unroll
                for (int j = 0; j < 8; j++)
                    acc[i][j] += a[i] * b[j];
        }
        __syncthreads();
    }

    #pragma unroll
    for (int i = 0; i < 8; i++) {
        int r = rowBase + ty * 8 + i;
        if (r < M) {
            float4* o = (float4*)(out + (size_t)r * MICRO_DIM + colBase + tx * 8);
            o[0] = make_float4(acc[i][0], acc[i][1], acc[i][2], acc[i][3]);
            o[1] = make_float4(acc[i][4], acc[i][5], acc[i][6], acc[i][7]);
        }
    }
}

// ---------------- 6) bias + LayerNorm + exact GELU, warp per row, in-place ----------------
__global__ void __launch_bounds__(256)
ln_gelu_kernel(const float* __restrict__ pb,
               const float* __restrict__ lng,
               const float* __restrict__ lnb,
               float* __restrict__ out, int M) {
    int row  = blockIdx.x * 8 + (threadIdx.x >> 5);
    int lane = threadIdx.x & 31;
    if (row >= M) return;

    float4* p = (float4*)(out + (size_t)row * MICRO_DIM);
    const float4* pb4 = (const float4*)pb;
    float x[16];
    float sum = 0.f;
    #pragma unroll
    for (int k = 0; k < 4; k++) {
        float4 h = p[lane + 32 * k];
        float4 b = pb4[lane + 32 * k];
        x[4*k+0] = h.x + b.x; x[4*k+1] = h.y + b.y;
        x[4*k+2] = h.z + b.z; x[4*k+3] = h.w + b.w;
        sum += x[4*k] + x[4*k+1] + x[4*k+2] + x[4*k+3];
    }
    #pragma unroll
    for (int d = 16; d; d >>= 1) sum += __shfl_xor_sync(0xffffffffu, sum, d);
    float mu = sum * (1.f / 512.f);

    float v = 0.f;
    #pragma unroll
    for (int i = 0; i < 16; i++) { float dlt = x[i] - mu; v += dlt * dlt; }
    #pragma unroll
    for (int d = 16; d; d >>= 1) v += __shfl_xor_sync(0xffffffffu, v, d);
    v *= (1.f / 512.f);
    float rs = rsqrtf(v + EPS_LN);

    const float4* g4 = (const float4*)lng;
    const float4* b4 = (const float4*)lnb;
    #pragma unroll
    for (int k = 0; k < 4; k++) {
        float4 gg = g4[lane + 32 * k];
        float4 bb = b4[lane + 32 * k];
        float4 o;
        float y;
        y = (x[4*k+0] - mu) * rs * gg.x + bb.x; o.x = 0.5f * y * (1.f + erff(y * 0.70710678118654752f));
        y = (x[4*k+1] - mu) * rs * gg.y + bb.y; o.y = 0.5f * y * (1.f + erff(y * 0.70710678118654752f));
        y = (x[4*k+2] - mu) * rs * gg.z + bb.z; o.z = 0.5f * y * (1.f + erff(y * 0.70710678118654752f));
        y = (x[4*k+3] - mu) * rs * gg.w + bb.w; o.w = 0.5f * y * (1.f + erff(y * 0.70710678118654752f));
        p[lane + 32 * k] = o;
    }
}

// ---------------- launch ----------------
extern "C" void kernel_launch(void* const* d_in, const int* in_sizes, int n_in,
                              void* d_out, int out_size) {
    const float* feat   = (const float*)d_in[0];
    const float* attn_w = (const float*)d_in[1];
    const float* attn_b = (const float*)d_in[2];
    const float* proj_w = (const float*)d_in[3];
    const float* proj_b = (const float*)d_in[4];
    const float* ln_g   = (const float*)d_in[5];
    const float* ln_b   = (const float*)d_in[6];
    const int*   m2m    = (const int*)d_in[7];
    int n = in_sizes[7];
    float* out = (float*)d_out;

    init_kernel<<<(NSEG + 255) / 256, 256>>>();
    count_kernel<<<(n + 255) / 256, 256>>>(m2m, n);
    sum_chunks_kernel<<<NB_CHUNK, 256>>>();
    scan_bsums_kernel<<<1, 32>>>();
    scan_chunks_kernel<<<NB_CHUNK, 32>>>();
    scatter_kernel<<<(n + 255) / 256, 256>>>(m2m, n);
    agg_kernel<<<NSEG, 256>>>(feat, attn_w, attn_b);

    dim3 ggrid(MICRO_DIM / BN, NSEG_PAD / BM);   // (4, 469)
    gemm_kernel<<<ggrid, 256>>>(proj_w, out, NSEG);

    ln_gelu_kernel<<<(NSEG + 7) / 8, 256>>>(proj_b, ln_g, ln_b, out, NSEG);
}

// round 4
// speedup vs baseline: 1.4662x; 1.4662x over previous
#include <cuda_runtime.h>
#include <cuda_bf16.h>
#include <math.h>
#include <stdint.h>

// ---------------- problem constants ----------------
#define N_MICRO_MAX 500000
#define MICRO_DIM   512
#define N_NODES_C   20000
#define N_EDGES_C   40000
#define NSEG        60000
#define NSEG_PAD    60032          // 469 * 128
#define EPS_SM      1e-8f
#define EPS_LN      1e-5f

#define CHUNK       1024
#define NB_CHUNK    59

#define CACHE_ROWS  20
#define MAX_SH      1024

// ---------------- device scratch ----------------
__device__ int   g_counts[NSEG];
__device__ int   g_offsets[NSEG];
__device__ int   g_cursor[NSEG];
__device__ int   g_bsum[NB_CHUNK];
__device__ int   g_rows[N_MICRO_MAX];
__device__ float g_agg[(size_t)NSEG_PAD * MICRO_DIM];        // zero-init; pad rows never written
__device__ __nv_bfloat16 g_wt_hi[MICRO_DIM * MICRO_DIM];     // W^T [N][K], bf16 hi
__device__ __nv_bfloat16 g_wt_lo[MICRO_DIM * MICRO_DIM];     // W^T [N][K], bf16 lo

// ---------------- helpers ----------------
__device__ __forceinline__ uint32_t smem_u32(const void* p) {
    uint32_t a;
    asm("{ .reg .u64 t; cvta.to.shared.u64 t, %1; cvt.u32.u64 %0, t; }" : "=r"(a) : "l"(p));
    return a;
}

__device__ __forceinline__ int seg_of(int m) {
    if (m >= 0) return m;
    if (m == -100) return -1;
    return N_NODES_C + (-m - 1);
}

__device__ __forceinline__ void ldsm4(uint32_t* r, uint32_t addr) {
    asm volatile("ldmatrix.sync.aligned.m8n8.x4.shared.b16 {%0,%1,%2,%3}, [%4];"
        : "=r"(r[0]), "=r"(r[1]), "=r"(r[2]), "=r"(r[3]) : "r"(addr));
}

__device__ __forceinline__ void mma_bf16(float* d, const uint32_t* a, const uint32_t* b) {
    asm volatile("mma.sync.aligned.m16n8k16.row.col.f32.bf16.bf16.f32 "
        "{%0,%1,%2,%3},{%4,%5,%6,%7},{%8,%9},{%0,%1,%2,%3};"
        : "+f"(d[0]), "+f"(d[1]), "+f"(d[2]), "+f"(d[3])
        : "r"(a[0]), "r"(a[1]), "r"(a[2]), "r"(a[3]), "r"(b[0]), "r"(b[1]));
}

// ---------------- 0) init scratch ----------------
__global__ void init_kernel() {
    int i = blockIdx.x * blockDim.x + threadIdx.x;
    if (i < NSEG) { g_counts[i] = 0; g_cursor[i] = 0; }
}

// ---------------- 1) count ----------------
__global__ void count_kernel(const int* __restrict__ m2m, int n) {
    int i = blockIdx.x * blockDim.x + threadIdx.x;
    if (i < n) {
        int s = seg_of(m2m[i]);
        if (s >= 0) atomicAdd(&g_counts[s], 1);
    }
}

// ---------------- 2) scan ----------------
__global__ void sum_chunks_kernel() {
    __shared__ int sh[256];
    int b = blockIdx.x, t = threadIdx.x;
    int base = b * CHUNK;
    int s = 0;
    for (int j = t; j < CHUNK; j += 256) {
        int i = base + j;
        if (i < NSEG) s += g_counts[i];
    }
    sh[t] = s; __syncthreads();
    for (int d = 128; d; d >>= 1) { if (t < d) sh[t] += sh[t + d]; __syncthreads(); }
    if (t == 0) g_bsum[b] = sh[0];
}

__global__ void scan_bsums_kernel() {
    if (threadIdx.x == 0 && blockIdx.x == 0) {
        int c = 0;
        for (int b = 0; b < NB_CHUNK; b++) { int v = g_bsum[b]; g_bsum[b] = c; c += v; }
    }
}

__global__ void scan_chunks_kernel() {
    int b = blockIdx.x, lane = threadIdx.x;
    int base = b * CHUNK + lane * 32;
    int vals[32];
    int lsum = 0;
    #pragma unroll
    for (int j = 0; j < 32; j++) {
        int i = base + j;
        vals[j] = (i < NSEG) ? g_counts[i] : 0;
        lsum += vals[j];
    }
    int pre = lsum;
    #pragma unroll
    for (int d = 1; d < 32; d <<= 1) {
        int x = __shfl_up_sync(0xffffffffu, pre, d);
        if (lane >= d) pre += x;
    }
    pre -= lsum;
    int carry = g_bsum[b] + pre;
    #pragma unroll
    for (int j = 0; j < 32; j++) {
        int i = base + j;
        if (i < NSEG) g_offsets[i] = carry;
        carry += vals[j];
    }
}

// ---------------- 3) scatter ----------------
__global__ void scatter_kernel(const int* __restrict__ m2m, int n) {
    int i = blockIdx.x * blockDim.x + threadIdx.x;
    if (i < n) {
        int s = seg_of(m2m[i]);
        if (s >= 0) {
            int pos = g_offsets[s] + atomicAdd(&g_cursor[s], 1);
            g_rows[pos] = i;
        }
    }
}

// ---------------- 3b) W transpose + bf16 hi/lo split ----------------
__global__ void wsplit_kernel(const float* __restrict__ W) {
    int i = blockIdx.x * blockDim.x + threadIdx.x;   // i = k*512 + n
    int k = i >> 9, n = i & 511;
    float v = W[i];
    __nv_bfloat16 hi = __float2bfloat16_rn(v);
    __nv_bfloat16 lo = __float2bfloat16_rn(v - __bfloat162float(hi));
    g_wt_hi[n * MICRO_DIM + k] = hi;
    g_wt_lo[n * MICRO_DIM + k] = lo;
}

// ---------------- 4) per-segment fused softmax aggregation ----------------
__global__ void __launch_bounds__(256)
agg_kernel(const float* __restrict__ feat,
           const float* __restrict__ attn_w,
           const float* __restrict__ attn_bp) {
    __shared__ float s_aw[MICRO_DIM];
    __shared__ float s_rows[CACHE_ROWS][MICRO_DIM];
    __shared__ float s_logit[MAX_SH];
    __shared__ float s_red[8];

    int seg  = blockIdx.x;
    int tid  = threadIdx.x;
    int lane = tid & 31, wid = tid >> 5;
    int cnt  = g_counts[seg];
    int off  = g_offsets[seg];
    int c0 = tid, c1 = tid + 256;
    size_t outbase = (size_t)seg * MICRO_DIM;

    if (cnt == 0) {
        g_agg[outbase + c0] = 0.f;
        g_agg[outbase + c1] = 0.f;
        return;
    }

    for (int j = tid; j < MICRO_DIM; j += 256) s_aw[j] = attn_w[j];
    __syncthreads();
    float ab = attn_bp[0];
    float acc0 = 0.f, acc1 = 0.f;

    if (cnt <= MAX_SH) {
        for (int r = wid; r < cnt; r += 8) {
            int row = g_rows[off + r];
            const float4* fp = (const float4*)(feat + (size_t)row * MICRO_DIM);
            float dot = 0.f;
            bool cache = (r < CACHE_ROWS);
            #pragma unroll
            for (int k = 0; k < 4; k++) {
                float4 v = fp[lane + 32 * k];
                int j = (lane + 32 * k) * 4;
                dot += v.x * s_aw[j] + v.y * s_aw[j + 1] + v.z * s_aw[j + 2] + v.w * s_aw[j + 3];
                if (cache) ((float4*)s_rows[r])[lane + 32 * k] = v;
            }
            #pragma unroll
            for (int d = 16; d; d >>= 1) dot += __shfl_xor_sync(0xffffffffu, dot, d);
            if (lane == 0) s_logit[r] = dot + ab;
        }
        __syncthreads();

        float m = -INFINITY;
        for (int r = tid; r < cnt; r += 256) m = fmaxf(m, s_logit[r]);
        #pragma unroll
        for (int d = 16; d; d >>= 1) m = fmaxf(m, __shfl_xor_sync(0xffffffffu, m, d));
        if (lane == 0) s_red[wid] = m;
        __syncthreads();
        m = s_red[0];
        #pragma unroll
        for (int w = 1; w < 8; w++) m = fmaxf(m, s_red[w]);
        __syncthreads();

        float ssum = 0.f;
        for (int r = tid; r < cnt; r += 256) {
            float e = expf(s_logit[r] - m);
            s_logit[r] = e;
            ssum += e;
        }
        #pragma unroll
        for (int d = 16; d; d >>= 1) ssum += __shfl_xor_sync(0xffffffffu, ssum, d);
        if (lane == 0) s_red[wid] = ssum;
        __syncthreads();
        float tot = 0.f;
        #pragma unroll
        for (int w = 0; w < 8; w++) tot += s_red[w];
        float inv = 1.f / (tot + EPS_SM);

        for (int r = 0; r < cnt; r++) {
            float wgt = s_logit[r] * inv;
            if (r < CACHE_ROWS) {
                acc0 += wgt * s_rows[r][c0];
                acc1 += wgt * s_rows[r][c1];
            } else {
                int row = g_rows[off + r];
                acc0 += wgt * __ldg(feat + (size_t)row * MICRO_DIM + c0);
                acc1 += wgt * __ldg(feat + (size_t)row * MICRO_DIM + c1);
            }
        }
    } else {
        float m = -INFINITY, s = 0.f;
        for (int r = 0; r < cnt; r++) {
            int row = g_rows[off + r];
            const float* f = feat + (size_t)row * MICRO_DIM;
            float f0 = f[c0], f1 = f[c1];
            float p = f0 * s_aw[c0] + f1 * s_aw[c1];
            #pragma unroll
            for (int d = 16; d; d >>= 1) p += __shfl_xor_sync(0xffffffffu, p, d);
            if (lane == 0) s_red[wid] = p;
            __syncthreads();
            float l = ab;
            #pragma unroll
            for (int w = 0; w < 8; w++) l += s_red[w];
            __syncthreads();
            float mn = fmaxf(m, l);
            float sc = expf(m - mn);
            float e  = expf(l - mn);
            s    = s * sc + e;
            acc0 = acc0 * sc + e * f0;
            acc1 = acc1 * sc + e * f1;
            m = mn;
        }
        float inv = 1.f / (s + EPS_SM);
        acc0 *= inv; acc1 *= inv;
    }

    g_agg[outbase + c0] = acc0;
    g_agg[outbase + c1] = acc1;
}

// ---------------- 5) mma.sync bf16 3-split GEMM: out = g_agg @ W ----------------
// CTA tile 128x128, K-chunk 32, 8 warps (4 x 2), warp tile 32x64.
// SMEM tile rows padded to 80B for conflict-free ldmatrix.
#define GTILE_M   128
#define GTILE_N   128
#define GKC       32
#define GNCHUNK   16
#define ROWB      80                        // bytes per smem tile row (64 data + 16 pad)
#define A_HI_OFF  0
#define A_LO_OFF  (128 * ROWB)              // 10240
#define B_HI_OFF  (2 * 128 * ROWB)          // 20480
#define B_LO_OFF  (3 * 128 * ROWB)          // 30720
#define STAGE_SZ  (4 * 128 * ROWB)          // 40960
#define SMEM_GEMM (2 * STAGE_SZ)            // 81920

__global__ void __launch_bounds__(256)
gemm_mma_kernel(float* __restrict__ out, int M) {
    extern __shared__ char smem[];
    uint32_t sbase = smem_u32(smem);

    int tid  = threadIdx.x;
    int lane = tid & 31, wid = tid >> 5;
    int warp_m = wid & 3;          // 0..3 -> 32-row slices
    int warp_n = wid >> 2;         // 0..1 -> 64-col slices
    int rowBase = blockIdx.y * GTILE_M;
    int colBase = blockIdx.x * GTILE_N;

    float acc[2][8][4];
    #pragma unroll
    for (int i = 0; i < 2; i++)
        #pragma unroll
        for (int j = 0; j < 8; j++)
            #pragma unroll
            for (int q = 0; q < 4; q++) acc[i][j][q] = 0.f;

    // per-thread staging indices
    // A: 1024 float4 per chunk -> 4 each: r = f>>3 (row), q = f&7 (float4 within row)
    // B: 512 uint4 per matrix per chunk -> 2 each: n = f>>2, q = f&3
    float4 aReg[4];
    uint4  bRegH[2], bRegL[2];

    // ldmatrix lane addressing (within-tile offsets, depend only on lane)
    int a_r = (lane & 7) + ((lane >> 3) & 1) * 8;   // row within 16-row tile
    int a_o = (lane >> 4) * 16;                     // 0 or 16 bytes (k 0-7 / 8-15)
    int b_r = (lane & 7) + ((lane >> 4) & 1) * 8;   // row within 16-n-row block
    int b_o = ((lane >> 3) & 1) * 16;

    #define LDG_CHUNK(c) do {                                                          \
        int k0 = (c) * GKC;                                                            \
        _Pragma("unroll")                                                              \
        for (int i = 0; i < 4; i++) {                                                  \
            int f = tid + i * 256; int r = f >> 3; int q = f & 7;                      \
            aReg[i] = *(const float4*)(g_agg + (size_t)(rowBase + r) * MICRO_DIM + k0 + q * 4); \
        }                                                                              \
        _Pragma("unroll")                                                              \
        for (int i = 0; i < 2; i++) {                                                  \
            int f = tid + i * 256; int n = f >> 2; int q = f & 3;                      \
            size_t e = ((size_t)(colBase + n) * MICRO_DIM + k0);                       \
            bRegH[i] = ((const uint4*)g_wt_hi)[e / 8 + q];                             \
            bRegL[i] = ((const uint4*)g_wt_lo)[e / 8 + q];                             \
        }                                                                              \
    } while (0)

    #define STS_CHUNK(buf) do {                                                        \
        char* bp = smem + (buf) * STAGE_SZ;                                            \
        _Pragma("unroll")                                                              \
        for (int i = 0; i < 4; i++) {                                                  \
            int f = tid + i * 256; int r = f >> 3; int q = f & 7;                      \
            float4 v = aReg[i];                                                        \
            __nv_bfloat162 h01 = __floats2bfloat162_rn(v.x, v.y);                      \
            __nv_bfloat162 h23 = __floats2bfloat162_rn(v.z, v.w);                      \
            __nv_bfloat162 l01 = __floats2bfloat162_rn(v.x - __bfloat162float(h01.x),  \
                                                       v.y - __bfloat162float(h01.y)); \
            __nv_bfloat162 l23 = __floats2bfloat162_rn(v.z - __bfloat162float(h23.x),  \
                                                       v.w - __bfloat162float(h23.y)); \
            uint2 hv = make_uint2(*(uint32_t*)&h01, *(uint32_t*)&h23);                 \
            uint2 lv = make_uint2(*(uint32_t*)&l01, *(uint32_t*)&l23);                 \
            *(uint2*)(bp + A_HI_OFF + r * ROWB + q * 8) = hv;                          \
            *(uint2*)(bp + A_LO_OFF + r * ROWB + q * 8) = lv;                          \
        }                                                                              \
        _Pragma("unroll")                                                              \
        for (int i = 0; i < 2; i++) {                                                  \
            int f = tid + i * 256; int n = f >> 2; int q = f & 3;                      \
            *(uint4*)(bp + B_HI_OFF + n * ROWB + q * 16) = bRegH[i];                   \
            *(uint4*)(bp + B_LO_OFF + n * ROWB + q * 16) = bRegL[i];                   \
        }                                                                              \
    } while (0)

    LDG_CHUNK(0);
    STS_CHUNK(0);
    __syncthreads();

    for (int c = 0; c < GNCHUNK; c++) {
        if (c + 1 < GNCHUNK) LDG_CHUNK(c + 1);

        uint32_t stage = sbase + (c & 1) * STAGE_SZ;
        #pragma unroll
        for (int s = 0; s < 2; s++) {
            uint32_t ah[2][4], al[2][4];
            #pragma unroll
            for (int mm = 0; mm < 2; mm++) {
                uint32_t off = (uint32_t)((warp_m * 32 + mm * 16 + a_r) * ROWB + s * 32 + a_o);
                ldsm4(ah[mm], stage + A_HI_OFF + off);
                ldsm4(al[mm], stage + A_LO_OFF + off);
            }
            uint32_t bh[4][4], bl[4][4];
            #pragma unroll
            for (int p = 0; p < 4; p++) {
                uint32_t off = (uint32_t)((warp_n * 64 + p * 16 + b_r) * ROWB + s * 32 + b_o);
                ldsm4(bh[p], stage + B_HI_OFF + off);
                ldsm4(bl[p], stage + B_LO_OFF + off);
            }
            #pragma unroll
            for (int mm = 0; mm < 2; mm++) {
                #pragma unroll
                for (int nt = 0; nt < 8; nt++) {
                    const uint32_t* bph = &bh[nt >> 1][(nt & 1) * 2];
                    const uint32_t* bpl = &bl[nt >> 1][(nt & 1) * 2];
                    mma_bf16(acc[mm][nt], ah[mm], bph);
                    mma_bf16(acc[mm][nt], ah[mm], bpl);
                    mma_bf16(acc[mm][nt], al[mm], bph);
                }
            }
        }
        __syncthreads();
        if (c + 1 < GNCHUNK) {
            STS_CHUNK((c + 1) & 1);
            __syncthreads();
        }
    }

    // epilogue
    #pragma unroll
    for (int mm = 0; mm < 2; mm++) {
        int row0 = rowBase + warp_m * 32 + mm * 16 + (lane >> 2);
        #pragma unroll
        for (int nt = 0; nt < 8; nt++) {
            int col = colBase + warp_n * 64 + nt * 8 + (lane & 3) * 2;
            if (row0 < M)
                *(float2*)(out + (size_t)row0 * MICRO_DIM + col) =
                    make_float2(acc[mm][nt][0], acc[mm][nt][1]);
            if (row0 + 8 < M)
                *(float2*)(out + (size_t)(row0 + 8) * MICRO_DIM + col) =
                    make_float2(acc[mm][nt][2], acc[mm][nt][3]);
        }
    }
    #undef LDG_CHUNK
    #undef STS_CHUNK
}

// ---------------- 6) bias + LayerNorm + exact GELU ----------------
__global__ void __launch_bounds__(256)
ln_gelu_kernel(const float* __restrict__ pb,
               const float* __restrict__ lng,
               const float* __restrict__ lnb,
               float* __restrict__ out, int M) {
    int row  = blockIdx.x * 8 + (threadIdx.x >> 5);
    int lane = threadIdx.x & 31;
    if (row >= M) return;

    float4* p = (float4*)(out + (size_t)row * MICRO_DIM);
    const float4* pb4 = (const float4*)pb;
    float x[16];
    float sum = 0.f;
    #pragma unroll
    for (int k = 0; k < 4; k++) {
        float4 h = p[lane + 32 * k];
        float4 b = pb4[lane + 32 * k];
        x[4*k+0] = h.x + b.x; x[4*k+1] = h.y + b.y;
        x[4*k+2] = h.z + b.z; x[4*k+3] = h.w + b.w;
        sum += x[4*k] + x[4*k+1] + x[4*k+2] + x[4*k+3];
    }
    #pragma unroll
    for (int d = 16; d; d >>= 1) sum += __shfl_xor_sync(0xffffffffu, sum, d);
    float mu = sum * (1.f / 512.f);

    float v = 0.f;
    #pragma unroll
    for (int i = 0; i < 16; i++) { float dlt = x[i] - mu; v += dlt * dlt; }
    #pragma unroll
    for (int d = 16; d; d >>= 1) v += __shfl_xor_sync(0xffffffffu, v, d);
    v *= (1.f / 512.f);
    float rs = rsqrtf(v + EPS_LN);

    const float4* g4 = (const float4*)lng;
    const float4* b4 = (const float4*)lnb;
    #pragma unroll
    for (int k = 0; k < 4; k++) {
        float4 gg = g4[lane + 32 * k];
        float4 bb = b4[lane + 32 * k];
        float4 o;
        float y;
        y = (x[4*k+0] - mu) * rs * gg.x + bb.x; o.x = 0.5f * y * (1.f + erff(y * 0.70710678118654752f));
        y = (x[4*k+1] - mu) * rs * gg.y + bb.y; o.y = 0.5f * y * (1.f + erff(y * 0.70710678118654752f));
        y = (x[4*k+2] - mu) * rs * gg.z + bb.z; o.z = 0.5f * y * (1.f + erff(y * 0.70710678118654752f));
        y = (x[4*k+3] - mu) * rs * gg.w + bb.w; o.w = 0.5f * y * (1.f + erff(y * 0.70710678118654752f));
        p[lane + 32 * k] = o;
    }
}

// ---------------- launch ----------------
extern "C" void kernel_launch(void* const* d_in, const int* in_sizes, int n_in,
                              void* d_out, int out_size) {
    const float* feat   = (const float*)d_in[0];
    const float* attn_w = (const float*)d_in[1];
    const float* attn_b = (const float*)d_in[2];
    const float* proj_w = (const float*)d_in[3];
    const float* proj_b = (const float*)d_in[4];
    const float* ln_g   = (const float*)d_in[5];
    const float* ln_b   = (const float*)d_in[6];
    const int*   m2m    = (const int*)d_in[7];
    int n = in_sizes[7];
    float* out = (float*)d_out;

    static bool attr_done = false;
    if (!attr_done) {
        cudaFuncSetAttribute(gemm_mma_kernel,
                             cudaFuncAttributeMaxDynamicSharedMemorySize, SMEM_GEMM);
        attr_done = true;
    }

    init_kernel<<<(NSEG + 255) / 256, 256>>>();
    count_kernel<<<(n + 255) / 256, 256>>>(m2m, n);
    sum_chunks_kernel<<<NB_CHUNK, 256>>>();
    scan_bsums_kernel<<<1, 32>>>();
    scan_chunks_kernel<<<NB_CHUNK, 32>>>();
    scatter_kernel<<<(n + 255) / 256, 256>>>(m2m, n);
    wsplit_kernel<<<(MICRO_DIM * MICRO_DIM) / 256, 256>>>(proj_w);
    agg_kernel<<<NSEG, 256>>>(feat, attn_w, attn_b);

    dim3 ggrid(MICRO_DIM / GTILE_N, NSEG_PAD / GTILE_M);   // (4, 469)
    gemm_mma_kernel<<<ggrid, 256, SMEM_GEMM>>>(out, NSEG);

    ln_gelu_kernel<<<(NSEG + 7) / 8, 256>>>(proj_b, ln_g, ln_b, out, NSEG);
}

// round 5
// speedup vs baseline: 1.7001x; 1.1595x over previous
#include <cuda_runtime.h>
#include <cuda_bf16.h>
#include <math.h>
#include <stdint.h>

// ---------------- problem constants ----------------
#define N_MICRO_MAX 500000
#define MICRO_DIM   512
#define N_NODES_C   20000
#define N_EDGES_C   40000
#define NSEG        60000
#define NSEG_PAD    60032          // 469 * 128
#define EPS_SM      1e-8f
#define EPS_LN      1e-5f

#define CHUNK       1024
#define NB_CHUNK    59

#define CACHE_ROWS  12
#define MAX_SH      1024

// ---------------- device scratch ----------------
__device__ int   g_counts[NSEG];
__device__ int   g_offsets[NSEG];
__device__ int   g_cursor[NSEG];
__device__ int   g_bsum[NB_CHUNK];
__device__ int   g_rows[N_MICRO_MAX];
__device__ __align__(128) __nv_bfloat16 g_a_hi[(size_t)NSEG_PAD * MICRO_DIM];  // A bf16 hi (zero-init pad)
__device__ __align__(128) __nv_bfloat16 g_a_lo[(size_t)NSEG_PAD * MICRO_DIM];  // A bf16 lo
__device__ __align__(128) __nv_bfloat16 g_wt_hi[MICRO_DIM * MICRO_DIM];        // W^T [N][K], bf16 hi
__device__ __align__(128) __nv_bfloat16 g_wt_lo[MICRO_DIM * MICRO_DIM];        // W^T [N][K], bf16 lo

// ---------------- helpers ----------------
__device__ __forceinline__ uint32_t smem_u32(const void* p) {
    uint32_t a;
    asm("{ .reg .u64 t; cvta.to.shared.u64 t, %1; cvt.u32.u64 %0, t; }" : "=r"(a) : "l"(p));
    return a;
}

__device__ __forceinline__ int seg_of(int m) {
    if (m >= 0) return m;
    if (m == -100) return -1;
    return N_NODES_C + (-m - 1);
}

__device__ __forceinline__ void ldsm4(uint32_t* r, uint32_t addr) {
    asm volatile("ldmatrix.sync.aligned.m8n8.x4.shared.b16 {%0,%1,%2,%3}, [%4];"
        : "=r"(r[0]), "=r"(r[1]), "=r"(r[2]), "=r"(r[3]) : "r"(addr));
}

__device__ __forceinline__ void mma_bf16(float* d, const uint32_t* a, const uint32_t* b) {
    asm volatile("mma.sync.aligned.m16n8k16.row.col.f32.bf16.bf16.f32 "
        "{%0,%1,%2,%3},{%4,%5,%6,%7},{%8,%9},{%0,%1,%2,%3};"
        : "+f"(d[0]), "+f"(d[1]), "+f"(d[2]), "+f"(d[3])
        : "r"(a[0]), "r"(a[1]), "r"(a[2]), "r"(a[3]), "r"(b[0]), "r"(b[1]));
}

#define CP_ASYNC16(dst, src) \
    asm volatile("cp.async.cg.shared.global [%0], [%1], 16;" :: "r"(dst), "l"(src))
#define CP_COMMIT() asm volatile("cp.async.commit_group;" ::: "memory")
#define CP_WAIT1()  asm volatile("cp.async.wait_group 1;" ::: "memory")
#define CP_WAIT0()  asm volatile("cp.async.wait_group 0;" ::: "memory")

// ---------------- 0) init scratch ----------------
__global__ void init_kernel() {
    int i = blockIdx.x * blockDim.x + threadIdx.x;
    if (i < NSEG) { g_counts[i] = 0; g_cursor[i] = 0; }
}

// ---------------- 1) count ----------------
__global__ void count_kernel(const int* __restrict__ m2m, int n) {
    int i = blockIdx.x * blockDim.x + threadIdx.x;
    if (i < n) {
        int s = seg_of(m2m[i]);
        if (s >= 0) atomicAdd(&g_counts[s], 1);
    }
}

// ---------------- 2) scan ----------------
__global__ void sum_chunks_kernel() {
    __shared__ int sh[256];
    int b = blockIdx.x, t = threadIdx.x;
    int base = b * CHUNK;
    int s = 0;
    for (int j = t; j < CHUNK; j += 256) {
        int i = base + j;
        if (i < NSEG) s += g_counts[i];
    }
    sh[t] = s; __syncthreads();
    for (int d = 128; d; d >>= 1) { if (t < d) sh[t] += sh[t + d]; __syncthreads(); }
    if (t == 0) g_bsum[b] = sh[0];
}

__global__ void scan_bsums_kernel() {
    if (threadIdx.x == 0 && blockIdx.x == 0) {
        int c = 0;
        for (int b = 0; b < NB_CHUNK; b++) { int v = g_bsum[b]; g_bsum[b] = c; c += v; }
    }
}

__global__ void scan_chunks_kernel() {
    int b = blockIdx.x, lane = threadIdx.x;
    int base = b * CHUNK + lane * 32;
    int vals[32];
    int lsum = 0;
    #pragma unroll
    for (int j = 0; j < 32; j++) {
        int i = base + j;
        vals[j] = (i < NSEG) ? g_counts[i] : 0;
        lsum += vals[j];
    }
    int pre = lsum;
    #pragma unroll
    for (int d = 1; d < 32; d <<= 1) {
        int x = __shfl_up_sync(0xffffffffu, pre, d);
        if (lane >= d) pre += x;
    }
    pre -= lsum;
    int carry = g_bsum[b] + pre;
    #pragma unroll
    for (int j = 0; j < 32; j++) {
        int i = base + j;
        if (i < NSEG) g_offsets[i] = carry;
        carry += vals[j];
    }
}

// ---------------- 3) scatter ----------------
__global__ void scatter_kernel(const int* __restrict__ m2m, int n) {
    int i = blockIdx.x * blockDim.x + threadIdx.x;
    if (i < n) {
        int s = seg_of(m2m[i]);
        if (s >= 0) {
            int pos = g_offsets[s] + atomicAdd(&g_cursor[s], 1);
            g_rows[pos] = i;
        }
    }
}

// ---------------- 3b) W transpose + bf16 hi/lo split ----------------
__global__ void wsplit_kernel(const float* __restrict__ W) {
    int i = blockIdx.x * blockDim.x + threadIdx.x;   // i = k*512 + n
    int k = i >> 9, n = i & 511;
    float v = W[i];
    __nv_bfloat16 hi = __float2bfloat16_rn(v);
    __nv_bfloat16 lo = __float2bfloat16_rn(v - __bfloat162float(hi));
    g_wt_hi[n * MICRO_DIM + k] = hi;
    g_wt_lo[n * MICRO_DIM + k] = lo;
}

// ---------------- 4) per-segment fused softmax aggregation ----------------
__global__ void __launch_bounds__(256, 6)
agg_kernel(const float* __restrict__ feat,
           const float* __restrict__ attn_w,
           const float* __restrict__ attn_bp) {
    __shared__ float s_aw[MICRO_DIM];
    __shared__ float s_rows[CACHE_ROWS][MICRO_DIM];
    __shared__ float s_logit[MAX_SH];
    __shared__ float s_red[8];

    int seg  = blockIdx.x;
    int tid  = threadIdx.x;
    int lane = tid & 31, wid = tid >> 5;
    int cnt  = g_counts[seg];
    int off  = g_offsets[seg];
    int c0 = tid, c1 = tid + 256;
    size_t outbase = (size_t)seg * MICRO_DIM;

    if (cnt == 0) {
        g_a_hi[outbase + c0] = __float2bfloat16_rn(0.f);
        g_a_hi[outbase + c1] = __float2bfloat16_rn(0.f);
        g_a_lo[outbase + c0] = __float2bfloat16_rn(0.f);
        g_a_lo[outbase + c1] = __float2bfloat16_rn(0.f);
        return;
    }

    for (int j = tid; j < MICRO_DIM; j += 256) s_aw[j] = attn_w[j];
    __syncthreads();
    float ab = attn_bp[0];
    float acc0 = 0.f, acc1 = 0.f;

    if (cnt <= MAX_SH) {
        for (int r = wid; r < cnt; r += 8) {
            int row = g_rows[off + r];
            const float4* fp = (const float4*)(feat + (size_t)row * MICRO_DIM);
            float dot = 0.f;
            bool cache = (r < CACHE_ROWS);
            #pragma unroll
            for (int k = 0; k < 4; k++) {
                float4 v = fp[lane + 32 * k];
                int j = (lane + 32 * k) * 4;
                dot += v.x * s_aw[j] + v.y * s_aw[j + 1] + v.z * s_aw[j + 2] + v.w * s_aw[j + 3];
                if (cache) ((float4*)s_rows[r])[lane + 32 * k] = v;
            }
            #pragma unroll
            for (int d = 16; d; d >>= 1) dot += __shfl_xor_sync(0xffffffffu, dot, d);
            if (lane == 0) s_logit[r] = dot + ab;
        }
        __syncthreads();

        float m = -INFINITY;
        for (int r = tid; r < cnt; r += 256) m = fmaxf(m, s_logit[r]);
        #pragma unroll
        for (int d = 16; d; d >>= 1) m = fmaxf(m, __shfl_xor_sync(0xffffffffu, m, d));
        if (lane == 0) s_red[wid] = m;
        __syncthreads();
        m = s_red[0];
        #pragma unroll
        for (int w = 1; w < 8; w++) m = fmaxf(m, s_red[w]);
        __syncthreads();

        float ssum = 0.f;
        for (int r = tid; r < cnt; r += 256) {
            float e = expf(s_logit[r] - m);
            s_logit[r] = e;
            ssum += e;
        }
        #pragma unroll
        for (int d = 16; d; d >>= 1) ssum += __shfl_xor_sync(0xffffffffu, ssum, d);
        if (lane == 0) s_red[wid] = ssum;
        __syncthreads();
        float tot = 0.f;
        #pragma unroll
        for (int w = 0; w < 8; w++) tot += s_red[w];
        float inv = 1.f / (tot + EPS_SM);

        for (int r = 0; r < cnt; r++) {
            float wgt = s_logit[r] * inv;
            if (r < CACHE_ROWS) {
                acc0 += wgt * s_rows[r][c0];
                acc1 += wgt * s_rows[r][c1];
            } else {
                int row = g_rows[off + r];
                acc0 += wgt * __ldg(feat + (size_t)row * MICRO_DIM + c0);
                acc1 += wgt * __ldg(feat + (size_t)row * MICRO_DIM + c1);
            }
        }
    } else {
        float m = -INFINITY, s = 0.f;
        for (int r = 0; r < cnt; r++) {
            int row = g_rows[off + r];
            const float* f = feat + (size_t)row * MICRO_DIM;
            float f0 = f[c0], f1 = f[c1];
            float p = f0 * s_aw[c0] + f1 * s_aw[c1];
            #pragma unroll
            for (int d = 16; d; d >>= 1) p += __shfl_xor_sync(0xffffffffu, p, d);
            if (lane == 0) s_red[wid] = p;
            __syncthreads();
            float l = ab;
            #pragma unroll
            for (int w = 0; w < 8; w++) l += s_red[w];
            __syncthreads();
            float mn = fmaxf(m, l);
            float sc = expf(m - mn);
            float e  = expf(l - mn);
            s    = s * sc + e;
            acc0 = acc0 * sc + e * f0;
            acc1 = acc1 * sc + e * f1;
            m = mn;
        }
        float inv = 1.f / (s + EPS_SM);
        acc0 *= inv; acc1 *= inv;
    }

    // bf16 hi/lo split stores (consecutive tid -> consecutive 2B: coalesced 64B/warp)
    __nv_bfloat16 h0 = __float2bfloat16_rn(acc0);
    __nv_bfloat16 h1 = __float2bfloat16_rn(acc1);
    g_a_hi[outbase + c0] = h0;
    g_a_hi[outbase + c1] = h1;
    g_a_lo[outbase + c0] = __float2bfloat16_rn(acc0 - __bfloat162float(h0));
    g_a_lo[outbase + c1] = __float2bfloat16_rn(acc1 - __bfloat162float(h1));
}

// ---------------- 5) mma.sync bf16 3-split GEMM with cp.async: out = A @ W ----------------
// CTA tile 128x128, K-chunk 32, 8 warps (4 x 2), warp tile 32x64.
// SMEM tile rows padded to 80B for conflict-free ldmatrix. 2-stage cp.async pipeline.
#define GTILE_M   128
#define GTILE_N   128
#define GKC       32
#define GNCHUNK   16
#define ROWB      80
#define MAT_SZ    (128 * ROWB)              // 10240 per matrix (A_hi/A_lo/B_hi/B_lo)
#define STAGE_SZ  (4 * MAT_SZ)              // 40960
#define SMEM_GEMM (2 * STAGE_SZ)            // 81920

__global__ void __launch_bounds__(256)
gemm_mma_kernel(float* __restrict__ out, int M) {
    extern __shared__ char smem[];
    uint32_t sbase = smem_u32(smem);

    int tid  = threadIdx.x;
    int lane = tid & 31, wid = tid >> 5;
    int warp_m = wid & 3;
    int warp_n = wid >> 2;
    int rowBase = blockIdx.y * GTILE_M;
    int colBase = blockIdx.x * GTILE_N;

    float acc[2][8][4];
    #pragma unroll
    for (int i = 0; i < 2; i++)
        #pragma unroll
        for (int j = 0; j < 8; j++)
            #pragma unroll
            for (int q = 0; q < 4; q++) acc[i][j][q] = 0.f;

    // per-thread cp.async slots: 2048 16B copies per chunk, 8 per thread
    const __nv_bfloat16* srcb[8];
    uint32_t dsto[8];
    #pragma unroll
    for (int i = 0; i < 8; i++) {
        int f = tid + i * 256;
        int mat = f >> 9;                // 0:A_hi 1:A_lo 2:B_hi 3:B_lo
        int w = f & 511;
        int r = w >> 2, q = w & 3;
        const __nv_bfloat16* base;
        if      (mat == 0) base = g_a_hi + (size_t)(rowBase + r) * MICRO_DIM;
        else if (mat == 1) base = g_a_lo + (size_t)(rowBase + r) * MICRO_DIM;
        else if (mat == 2) base = g_wt_hi + (size_t)(colBase + r) * MICRO_DIM;
        else               base = g_wt_lo + (size_t)(colBase + r) * MICRO_DIM;
        srcb[i] = base + q * 8;
        dsto[i] = (uint32_t)(mat * MAT_SZ + r * ROWB + q * 16);
    }

    #define ISSUE(c) do {                                                       \
        uint32_t sb = sbase + ((c) & 1) * STAGE_SZ;                             \
        int k0 = (c) * GKC;                                                     \
        _Pragma("unroll")                                                       \
        for (int i = 0; i < 8; i++) CP_ASYNC16(sb + dsto[i], srcb[i] + k0);     \
        CP_COMMIT();                                                            \
    } while (0)

    // ldmatrix lane addressing
    int a_r = (lane & 7) + ((lane >> 3) & 1) * 8;
    int a_o = (lane >> 4) * 16;
    int b_r = (lane & 7) + ((lane >> 4) & 1) * 8;
    int b_o = ((lane >> 3) & 1) * 16;

    ISSUE(0);

    for (int c = 0; c < GNCHUNK; c++) {
        if (c + 1 < GNCHUNK) { ISSUE(c + 1); CP_WAIT1(); }
        else                 { CP_WAIT0(); }
        __syncthreads();

        uint32_t stage = sbase + (c & 1) * STAGE_SZ;
        #pragma unroll
        for (int s = 0; s < 2; s++) {
            uint32_t ah[2][4], al[2][4];
            #pragma unroll
            for (int mm = 0; mm < 2; mm++) {
                uint32_t off = (uint32_t)((warp_m * 32 + mm * 16 + a_r) * ROWB + s * 32 + a_o);
                ldsm4(ah[mm], stage + 0 * MAT_SZ + off);
                ldsm4(al[mm], stage + 1 * MAT_SZ + off);
            }
            uint32_t bh[4][4], bl[4][4];
            #pragma unroll
            for (int p = 0; p < 4; p++) {
                uint32_t off = (uint32_t)((warp_n * 64 + p * 16 + b_r) * ROWB + s * 32 + b_o);
                ldsm4(bh[p], stage + 2 * MAT_SZ + off);
                ldsm4(bl[p], stage + 3 * MAT_SZ + off);
            }
            #pragma unroll
            for (int mm = 0; mm < 2; mm++) {
                #pragma unroll
                for (int nt = 0; nt < 8; nt++) {
                    const uint32_t* bph = &bh[nt >> 1][(nt & 1) * 2];
                    const uint32_t* bpl = &bl[nt >> 1][(nt & 1) * 2];
                    mma_bf16(acc[mm][nt], ah[mm], bph);
                    mma_bf16(acc[mm][nt], ah[mm], bpl);
                    mma_bf16(acc[mm][nt], al[mm], bph);
                }
            }
        }
        __syncthreads();   // stage (c&1) fully consumed before iter c+1 issues into it
    }

    // epilogue
    #pragma unroll
    for (int mm = 0; mm < 2; mm++) {
        int row0 = rowBase + warp_m * 32 + mm * 16 + (lane >> 2);
        #pragma unroll
        for (int nt = 0; nt < 8; nt++) {
            int col = colBase + warp_n * 64 + nt * 8 + (lane & 3) * 2;
            if (row0 < M)
                *(float2*)(out + (size_t)row0 * MICRO_DIM + col) =
                    make_float2(acc[mm][nt][0], acc[mm][nt][1]);
            if (row0 + 8 < M)
                *(float2*)(out + (size_t)(row0 + 8) * MICRO_DIM + col) =
                    make_float2(acc[mm][nt][2], acc[mm][nt][3]);
        }
    }
    #undef ISSUE
}

// ---------------- 6) bias + LayerNorm + exact GELU ----------------
__global__ void __launch_bounds__(256)
ln_gelu_kernel(const float* __restrict__ pb,
               const float* __restrict__ lng,
               const float* __restrict__ lnb,
               float* __restrict__ out, int M) {
    int row  = blockIdx.x * 8 + (threadIdx.x >> 5);
    int lane = threadIdx.x & 31;
    if (row >= M) return;

    float4* p = (float4*)(out + (size_t)row * MICRO_DIM);
    const float4* pb4 = (const float4*)pb;
    float x[16];
    float sum = 0.f;
    #pragma unroll
    for (int k = 0; k < 4; k++) {
        float4 h = p[lane + 32 * k];
        float4 b = pb4[lane + 32 * k];
        x[4*k+0] = h.x + b.x; x[4*k+1] = h.y + b.y;
        x[4*k+2] = h.z + b.z; x[4*k+3] = h.w + b.w;
        sum += x[4*k] + x[4*k+1] + x[4*k+2] + x[4*k+3];
    }
    #pragma unroll
    for (int d = 16; d; d >>= 1) sum += __shfl_xor_sync(0xffffffffu, sum, d);
    float mu = sum * (1.f / 512.f);

    float v = 0.f;
    #pragma unroll
    for (int i = 0; i < 16; i++) { float dlt = x[i] - mu; v += dlt * dlt; }
    #pragma unroll
    for (int d = 16; d; d >>= 1) v += __shfl_xor_sync(0xffffffffu, v, d);
    v *= (1.f / 512.f);
    float rs = rsqrtf(v + EPS_LN);

    const float4* g4 = (const float4*)lng;
    const float4* b4 = (const float4*)lnb;
    #pragma unroll
    for (int k = 0; k < 4; k++) {
        float4 gg = g4[lane + 32 * k];
        float4 bb = b4[lane + 32 * k];
        float4 o;
        float y;
        y = (x[4*k+0] - mu) * rs * gg.x + bb.x; o.x = 0.5f * y * (1.f + erff(y * 0.70710678118654752f));
        y = (x[4*k+1] - mu) * rs * gg.y + bb.y; o.y = 0.5f * y * (1.f + erff(y * 0.70710678118654752f));
        y = (x[4*k+2] - mu) * rs * gg.z + bb.z; o.z = 0.5f * y * (1.f + erff(y * 0.70710678118654752f));
        y = (x[4*k+3] - mu) * rs * gg.w + bb.w; o.w = 0.5f * y * (1.f + erff(y * 0.70710678118654752f));
        p[lane + 32 * k] = o;
    }
}

// ---------------- launch ----------------
extern "C" void kernel_launch(void* const* d_in, const int* in_sizes, int n_in,
                              void* d_out, int out_size) {
    const float* feat   = (const float*)d_in[0];
    const float* attn_w = (const float*)d_in[1];
    const float* attn_b = (const float*)d_in[2];
    const float* proj_w = (const float*)d_in[3];
    const float* proj_b = (const float*)d_in[4];
    const float* ln_g   = (const float*)d_in[5];
    const float* ln_b   = (const float*)d_in[6];
    const int*   m2m    = (const int*)d_in[7];
    int n = in_sizes[7];
    float* out = (float*)d_out;

    static bool attr_done = false;
    if (!attr_done) {
        cudaFuncSetAttribute(gemm_mma_kernel,
                             cudaFuncAttributeMaxDynamicSharedMemorySize, SMEM_GEMM);
        attr_done = true;
    }

    init_kernel<<<(NSEG + 255) / 256, 256>>>();
    count_kernel<<<(n + 255) / 256, 256>>>(m2m, n);
    sum_chunks_kernel<<<NB_CHUNK, 256>>>();
    scan_bsums_kernel<<<1, 32>>>();
    scan_chunks_kernel<<<NB_CHUNK, 32>>>();
    scatter_kernel<<<(n + 255) / 256, 256>>>(m2m, n);
    wsplit_kernel<<<(MICRO_DIM * MICRO_DIM) / 256, 256>>>(proj_w);
    agg_kernel<<<NSEG, 256>>>(feat, attn_w, attn_b);

    dim3 ggrid(MICRO_DIM / GTILE_N, NSEG_PAD / GTILE_M);   // (4, 469)
    gemm_mma_kernel<<<ggrid, 256, SMEM_GEMM>>>(out, NSEG);

    ln_gelu_kernel<<<(NSEG + 7) / 8, 256>>>(proj_b, ln_g, ln_b, out, NSEG);
}